// round 2
// baseline (speedup 1.0000x reference)
#include <cuda_runtime.h>
#include <math.h>

// ---------------- problem constants ----------------
#define BB   4
#define TT   512
#define VV   576
#define LL   256
#define HH   1024
#define NHH  16
#define HDD  64
#define II   4096
#define EE   8
#define KSEL_T 80     // cap for text stream: floor((1.25*512+7)/8)
#define KSEL_V 90     // cap for image stream: floor((1.25*576+7)/8)
#define SELCAP 96
#define LN_EPS 1e-5f

// ---------------- scratch (static device memory; no allocs allowed) ----------
__device__ float g_ln   [BB*TT*HH];
__device__ float g_q    [BB*TT*HH];
__device__ float g_cq   [BB*TT*HH];
__device__ float g_qkv  [BB*TT*3*HH];
__device__ float g_kv   [BB*VV*2*HH];
__device__ float g_scores[BB*NHH*TT*VV];       // max width VV=576
__device__ float g_attn [BB*TT*HH];
__device__ float g_h    [BB*EE*SELCAP*II];
__device__ float g_acc  [BB*VV*HH];
__device__ float g_ctx_img[BB*HH];
__device__ float g_ctx_txt[BB*HH];
__device__ float g_gb_img[BB*EE];
__device__ float g_gb_txt[BB*EE];
__device__ float g_probs_t[BB*TT*EE];
__device__ float g_probs_i[BB*VV*EE];
__device__ int   g_sel_t[BB*EE*SELCAP];
__device__ int   g_sel_i[BB*EE*SELCAP];
__device__ int   g_cnt  [BB*VV];

// ---------------- helpers ----------------
__device__ __forceinline__ float gelu_f(float x) {
    // jax.nn.gelu approximate=True (tanh)
    float x3 = x * x * x;
    return 0.5f * x * (1.0f + tanhf(0.7978845608028654f * (x + 0.044715f * x3)));
}

// Generic tiled GEMM: C[M,N] = alpha*(A @ B^T or A @ B) + bias + res, epilogues.
// TRANSB=true : B is [N,K] row-major (weights). TRANSB=false: B is [K,N] row-major.
// arow: optional gather map for A rows. crow: optional scatter map for C rows.
template<bool TRANSB, bool GELU_E, bool ATOMIC>
__device__ __forceinline__ void gemm_tile(
    const float* __restrict__ A, int lda, const int* __restrict__ arow,
    const float* __restrict__ Bp, int ldb,
    const float* __restrict__ bias, const float* __restrict__ res,
    float* __restrict__ C, int ldc, const int* __restrict__ crow,
    int M, int N, int K, float alpha)
{
    __shared__ float As[16][68];
    __shared__ float Bs[16][68];
    const int tid = threadIdx.x;
    const int tx = tid & 15, ty = tid >> 4;
    const int m0 = blockIdx.y * 64, n0 = blockIdx.x * 64;

    float acc[4][4];
#pragma unroll
    for (int i = 0; i < 4; i++)
#pragma unroll
        for (int j = 0; j < 4; j++) acc[i][j] = 0.0f;

    for (int k0 = 0; k0 < K; k0 += 16) {
#pragma unroll
        for (int i = 0; i < 4; i++) {
            int idx = tid + i * 256;
            int m = idx >> 4, k = idx & 15;
            int gm = m0 + m;
            float v = 0.0f;
            if (gm < M) {
                int row = arow ? arow[gm] : gm;
                v = A[(size_t)row * lda + k0 + k];
            }
            As[k][m] = v;
        }
#pragma unroll
        for (int i = 0; i < 4; i++) {
            int idx = tid + i * 256;
            int n, k;
            if (TRANSB) { n = idx >> 4; k = idx & 15; }
            else        { n = idx & 63; k = idx >> 6; }
            int gn = n0 + n;
            float v = 0.0f;
            if (gn < N)
                v = TRANSB ? Bp[(size_t)gn * ldb + k0 + k]
                           : Bp[(size_t)(k0 + k) * ldb + gn];
            Bs[k][n] = v;
        }
        __syncthreads();
#pragma unroll
        for (int kk = 0; kk < 16; kk++) {
            float av[4], wv[4];
#pragma unroll
            for (int i = 0; i < 4; i++) av[i] = As[kk][ty * 4 + i];
#pragma unroll
            for (int j = 0; j < 4; j++) wv[j] = Bs[kk][tx * 4 + j];
#pragma unroll
            for (int i = 0; i < 4; i++)
#pragma unroll
                for (int j = 0; j < 4; j++) acc[i][j] += av[i] * wv[j];
        }
        __syncthreads();
    }

#pragma unroll
    for (int i = 0; i < 4; i++) {
        int gm = m0 + ty * 4 + i;
        if (gm >= M) continue;
        int orow = crow ? crow[gm] : gm;
#pragma unroll
        for (int j = 0; j < 4; j++) {
            int gn = n0 + tx * 4 + j;
            if (gn >= N) continue;
            float v = acc[i][j] * alpha;
            if (bias) v += bias[gn];
            if (res)  v += res[(size_t)gm * ldc + gn];
            if (GELU_E) v = gelu_f(v);
            if (ATOMIC) atomicAdd(&C[(size_t)orow * ldc + gn], v);
            else        C[(size_t)orow * ldc + gn] = v;
        }
    }
}

// ---------------- kernels ----------------
__global__ __launch_bounds__(256) void k_sgemm(
    const float* A, int lda, const float* W, int ldw,
    const float* bias, const float* res,
    float* C, int ldc, int M, int N, int K)
{
    gemm_tile<true, false, false>(A, lda, nullptr, W, ldw, bias, res, C, ldc,
                                  nullptr, M, N, K, 1.0f);
}

__global__ __launch_bounds__(256) void k_scores(
    const float* Q, int qbs, int qld,
    const float* Kp, int kbs, int kld,
    float* S, int Tq, int Skv)
{
    int z = blockIdx.z; int b = z / NHH, h = z % NHH;
    gemm_tile<true, false, false>(
        Q + (size_t)b * qbs + h * HDD, qld, nullptr,
        Kp + (size_t)b * kbs + h * HDD, kld,
        nullptr, nullptr,
        S + (size_t)z * Tq * Skv, Skv, nullptr,
        Tq, Skv, HDD, 0.125f);
}

__global__ __launch_bounds__(256) void k_av(
    const float* P, const float* Vb, int vbs, int vld,
    float* O, int Tq, int Skv)
{
    int z = blockIdx.z; int b = z / NHH, h = z % NHH;
    gemm_tile<false, false, false>(
        P + (size_t)z * Tq * Skv, Skv, nullptr,
        Vb + (size_t)b * vbs + h * HDD, vld,
        nullptr, nullptr,
        O + (size_t)b * Tq * HH + h * HDD, HH, nullptr,
        Tq, HDD, Skv, 1.0f);
}

__global__ __launch_bounds__(256) void k_moe1(
    const float* X, const float* w1, const float* b1, const int* sel,
    float* Hb, int S, int ksel)
{
    int g = blockIdx.z, b = g / EE, e = g % EE;
    gemm_tile<true, true, false>(
        X + (size_t)b * S * HH, HH, sel + g * SELCAP,
        w1 + (size_t)e * II * HH, HH, b1 + (size_t)e * II, nullptr,
        Hb + (size_t)g * SELCAP * II, II, nullptr,
        ksel, II, HH, 1.0f);
}

__global__ __launch_bounds__(256) void k_moe2(
    const float* Hb, const float* w2, const float* b2, const int* sel,
    float* Acc, int S, int ksel)
{
    int g = blockIdx.z, b = g / EE, e = g % EE;
    gemm_tile<true, false, true>(
        Hb + (size_t)g * SELCAP * II, II, nullptr,
        w2 + (size_t)e * HH * II, II, b2 + (size_t)e * HH, nullptr,
        Acc + (size_t)b * S * HH, HH, sel + g * SELCAP,
        ksel, HH, II, 1.0f);
}

__global__ void k_ln(const float* X, const float* gg, const float* bb,
                     float* Y, int rows)
{
    int r = blockIdx.x;
    const float* x = X + (size_t)r * HH;
    float* y = Y + (size_t)r * HH;
    int tid = threadIdx.x;
    float s = 0.0f, s2 = 0.0f;
    for (int i = tid; i < HH; i += 256) { float v = x[i]; s += v; s2 += v * v; }
    __shared__ float r1[256], r2[256];
    r1[tid] = s; r2[tid] = s2; __syncthreads();
    for (int st = 128; st; st >>= 1) {
        if (tid < st) { r1[tid] += r1[tid + st]; r2[tid] += r2[tid + st]; }
        __syncthreads();
    }
    float mean = r1[0] * (1.0f / HH);
    float var  = r2[0] * (1.0f / HH) - mean * mean;
    float rstd = rsqrtf(var + LN_EPS);
    for (int i = tid; i < HH; i += 256)
        y[i] = (x[i] - mean) * rstd * gg[i] + bb[i];
}

__global__ void k_softmax(float* S, int W)
{
    int r = blockIdx.x;
    float* row = S + (size_t)r * W;
    int tid = threadIdx.x;
    __shared__ float red[256];
    float m = -3.0e38f;
    for (int i = tid; i < W; i += 256) m = fmaxf(m, row[i]);
    red[tid] = m; __syncthreads();
    for (int st = 128; st; st >>= 1) {
        if (tid < st) red[tid] = fmaxf(red[tid], red[tid + st]);
        __syncthreads();
    }
    m = red[0]; __syncthreads();
    float sum = 0.0f;
    for (int i = tid; i < W; i += 256) {
        float e = expf(row[i] - m);
        row[i] = e; sum += e;
    }
    red[tid] = sum; __syncthreads();
    for (int st = 128; st; st >>= 1) {
        if (tid < st) red[tid] += red[tid + st];
        __syncthreads();
    }
    float inv = 1.0f / red[0];
    for (int i = tid; i < W; i += 256) row[i] *= inv;
}

__global__ void k_mean(const float* X, float* ctx, int S)
{
    int b = blockIdx.x;
    for (int c = threadIdx.x; c < HH; c += blockDim.x) {
        float s = 0.0f;
        for (int j = 0; j < S; j++) s += X[(size_t)(b * S + j) * HH + c];
        ctx[b * HH + c] = s / (float)S;
    }
}

__global__ void k_ctxbias(const float* ctx, const float* gw, const float* gb,
                          float* outp)
{
    int g = blockIdx.x; int b = g / EE, e = g % EE;
    int tid = threadIdx.x;
    float s = 0.0f;
    for (int c = tid; c < HH; c += 256)
        s += ctx[b * HH + c] * gw[(size_t)e * 2 * HH + HH + c];
    __shared__ float red[256];
    red[tid] = s; __syncthreads();
    for (int st = 128; st; st >>= 1) {
        if (tid < st) red[tid] += red[tid + st];
        __syncthreads();
    }
    if (tid == 0) outp[g] = red[0] + gb[e];
}

__global__ void k_gate(const float* X, const float* gw, const float* cb,
                       float* probs, int S)
{
    int t = blockIdx.x; int b = t / S;
    const float* x = X + (size_t)t * HH;
    int tid = threadIdx.x;
    float part[EE];
#pragma unroll
    for (int e = 0; e < EE; e++) part[e] = 0.0f;
    for (int c = tid; c < HH; c += 256) {
        float xv = x[c];
#pragma unroll
        for (int e = 0; e < EE; e++) part[e] += xv * gw[(size_t)e * 2 * HH + c];
    }
    __shared__ float red[256];
    __shared__ float lg[EE];
    for (int e = 0; e < EE; e++) {
        red[tid] = part[e]; __syncthreads();
        for (int st = 128; st; st >>= 1) {
            if (tid < st) red[tid] += red[tid + st];
            __syncthreads();
        }
        if (tid == 0) lg[e] = red[0] + cb[b * EE + e];
        __syncthreads();
    }
    if (tid == 0) {
        float mx = lg[0];
#pragma unroll
        for (int e = 1; e < EE; e++) mx = fmaxf(mx, lg[e]);
        float sum = 0.0f, ex[EE];
#pragma unroll
        for (int e = 0; e < EE; e++) { ex[e] = expf(lg[e] - mx); sum += ex[e]; }
        float inv = 1.0f / sum;
#pragma unroll
        for (int e = 0; e < EE; e++) probs[(size_t)t * EE + e] = ex[e] * inv;
    }
}

__global__ void k_topk(const float* probs, int S, int ksel, int* sel)
{
    int g = blockIdx.x; int b = g / EE, e = g % EE;
    int tid = threadIdx.x;
    __shared__ float v[VV];
    __shared__ float bestv[256];
    __shared__ int   besti[256];
    for (int i = tid; i < S; i += 256) v[i] = probs[(size_t)(b * S + i) * EE + e];
    __syncthreads();
    for (int it = 0; it < ksel; it++) {
        float bv = -3.0e38f; int bi = S;
        for (int i = tid; i < S; i += 256) {
            float x = v[i];
            if (x > bv || (x == bv && i < bi)) { bv = x; bi = i; }
        }
        bestv[tid] = bv; besti[tid] = bi; __syncthreads();
        for (int st = 128; st; st >>= 1) {
            if (tid < st) {
                if (bestv[tid + st] > bestv[tid] ||
                    (bestv[tid + st] == bestv[tid] && besti[tid + st] < besti[tid])) {
                    bestv[tid] = bestv[tid + st];
                    besti[tid] = besti[tid + st];
                }
            }
            __syncthreads();
        }
        if (tid == 0) { sel[g * SELCAP + it] = besti[0]; v[besti[0]] = -1.0e30f; }
        __syncthreads();
    }
}

__global__ void k_count(const int* sel, int* cnt, int S, int ksel)
{
    int g = blockIdx.x; int b = g / EE;
    for (int j = threadIdx.x; j < ksel; j += blockDim.x)
        atomicAdd(&cnt[b * S + sel[g * SELCAP + j]], 1);
}

__global__ void k_combine(const float* base, const float* acc, const int* cnt,
                          float* outp, int n)
{
    int i = blockIdx.x * 256 + threadIdx.x;
    if (i < n) {
        int tok = i / HH;
        outp[i] = base[i] + acc[i] / fmaxf((float)cnt[tok], 1.0f);
    }
}

__global__ void k_fillf(float* p, int n)
{
    int i = blockIdx.x * 256 + threadIdx.x;
    if (i < n) p[i] = 0.0f;
}

__global__ void k_zeroi(int* p, int n)
{
    int i = blockIdx.x * 256 + threadIdx.x;
    if (i < n) p[i] = 0;
}

// ---------------- launch ----------------
extern "C" void kernel_launch(void* const* d_in, const int* in_sizes, int n_in,
                              void* d_out, int out_size)
{
    (void)in_sizes; (void)n_in; (void)out_size;
    const float* in_q      = (const float*)d_in[0];
    const float* in_img    = (const float*)d_in[1];
    const float* in_txt    = (const float*)d_in[2];
    const float* sa_w_in   = (const float*)d_in[3];
    const float* sa_b_in   = (const float*)d_in[4];
    const float* sa_w_out  = (const float*)d_in[5];
    const float* sa_b_out  = (const float*)d_in[6];
    const float* ca_w_in   = (const float*)d_in[7];
    const float* ca_b_in   = (const float*)d_in[8];
    const float* ca_w_out  = (const float*)d_in[9];
    const float* ca_b_out  = (const float*)d_in[10];
    const float* gate_img_w= (const float*)d_in[11];
    const float* gate_img_b= (const float*)d_in[12];
    const float* gate_txt_w= (const float*)d_in[13];
    const float* gate_txt_b= (const float*)d_in[14];
    const float* e_w1      = (const float*)d_in[15];
    const float* e_b1      = (const float*)d_in[16];
    const float* e_w2      = (const float*)d_in[17];
    const float* e_b2      = (const float*)d_in[18];
    const float* lnq_g     = (const float*)d_in[19];
    const float* lnq_b     = (const float*)d_in[20];
    const float* lnc_g     = (const float*)d_in[21];
    const float* lnc_b     = (const float*)d_in[22];
    const float* lnf_g     = (const float*)d_in[23];
    const float* lnf_b     = (const float*)d_in[24];
    float* out_q   = (float*)d_out;
    float* out_img = out_q + (size_t)BB * TT * HH;

    float *p_ln, *p_q, *p_cq, *p_qkv, *p_kv, *p_scores, *p_attn, *p_h, *p_acc;
    float *p_ctx_img, *p_ctx_txt, *p_gb_img, *p_gb_txt, *p_probs_t, *p_probs_i;
    int *p_sel_t, *p_sel_i, *p_cnt;
    cudaGetSymbolAddress((void**)&p_ln, g_ln);
    cudaGetSymbolAddress((void**)&p_q, g_q);
    cudaGetSymbolAddress((void**)&p_cq, g_cq);
    cudaGetSymbolAddress((void**)&p_qkv, g_qkv);
    cudaGetSymbolAddress((void**)&p_kv, g_kv);
    cudaGetSymbolAddress((void**)&p_scores, g_scores);
    cudaGetSymbolAddress((void**)&p_attn, g_attn);
    cudaGetSymbolAddress((void**)&p_h, g_h);
    cudaGetSymbolAddress((void**)&p_acc, g_acc);
    cudaGetSymbolAddress((void**)&p_ctx_img, g_ctx_img);
    cudaGetSymbolAddress((void**)&p_ctx_txt, g_ctx_txt);
    cudaGetSymbolAddress((void**)&p_gb_img, g_gb_img);
    cudaGetSymbolAddress((void**)&p_gb_txt, g_gb_txt);
    cudaGetSymbolAddress((void**)&p_probs_t, g_probs_t);
    cudaGetSymbolAddress((void**)&p_probs_i, g_probs_i);
    cudaGetSymbolAddress((void**)&p_sel_t, g_sel_t);
    cudaGetSymbolAddress((void**)&p_sel_i, g_sel_i);
    cudaGetSymbolAddress((void**)&p_cnt, g_cnt);

    // ---- self attention (pre-norm, residual) ----
    k_ln<<<BB * TT, 256>>>(in_q, lnq_g, lnq_b, p_ln, BB * TT);
    k_sgemm<<<dim3(3 * HH / 64, BB * TT / 64), 256>>>(
        p_ln, HH, sa_w_in, HH, sa_b_in, nullptr, p_qkv, 3 * HH,
        BB * TT, 3 * HH, HH);
    k_scores<<<dim3(TT / 64, TT / 64, BB * NHH), 256>>>(
        p_qkv, TT * 3 * HH, 3 * HH, p_qkv + HH, TT * 3 * HH, 3 * HH,
        p_scores, TT, TT);
    k_softmax<<<BB * NHH * TT, 256>>>(p_scores, TT);
    k_av<<<dim3(1, TT / 64, BB * NHH), 256>>>(
        p_scores, p_qkv + 2 * HH, TT * 3 * HH, 3 * HH, p_attn, TT, TT);
    k_sgemm<<<dim3(HH / 64, BB * TT / 64), 256>>>(
        p_attn, HH, sa_w_out, HH, sa_b_out, in_q, p_q, HH, BB * TT, HH, HH);

    // ---- cross attention to image tokens ----
    k_ln<<<BB * TT, 256>>>(p_q, lnc_g, lnc_b, p_ln, BB * TT);
    k_sgemm<<<dim3(HH / 64, BB * TT / 64), 256>>>(
        p_ln, HH, ca_w_in, HH, ca_b_in, nullptr, p_cq, HH, BB * TT, HH, HH);
    k_sgemm<<<dim3(2 * HH / 64, BB * VV / 64), 256>>>(
        in_img, HH, ca_w_in + (size_t)HH * HH, HH, ca_b_in + HH, nullptr,
        p_kv, 2 * HH, BB * VV, 2 * HH, HH);
    k_scores<<<dim3(VV / 64, TT / 64, BB * NHH), 256>>>(
        p_cq, TT * HH, HH, p_kv, VV * 2 * HH, 2 * HH, p_scores, TT, VV);
    k_softmax<<<BB * NHH * TT, 256>>>(p_scores, VV);
    k_av<<<dim3(1, TT / 64, BB * NHH), 256>>>(
        p_scores, p_kv + HH, VV * 2 * HH, 2 * HH, p_attn, TT, VV);
    k_sgemm<<<dim3(HH / 64, BB * TT / 64), 256>>>(
        p_attn, HH, ca_w_out, HH, ca_b_out, p_q, p_q, HH, BB * TT, HH, HH);

    // ---- gating contexts + probs ----
    k_mean<<<BB, 256>>>(in_img, p_ctx_img, VV);
    k_mean<<<BB, 256>>>(in_txt, p_ctx_txt, LL);
    k_ctxbias<<<BB * EE, 256>>>(p_ctx_txt, gate_img_w, gate_img_b, p_gb_img);
    k_ctxbias<<<BB * EE, 256>>>(p_ctx_img, gate_txt_w, gate_txt_b, p_gb_txt);
    k_gate<<<BB * VV, 256>>>(in_img, gate_img_w, p_gb_img, p_probs_i, VV);
    k_gate<<<BB * TT, 256>>>(p_q, gate_txt_w, p_gb_txt, p_probs_t, TT);
    k_topk<<<BB * EE, 256>>>(p_probs_t, TT, KSEL_T, p_sel_t);
    k_topk<<<BB * EE, 256>>>(p_probs_i, VV, KSEL_V, p_sel_i);

    // ---- text-stream MoE (input = LN(q, lnf)) ----
    k_ln<<<BB * TT, 256>>>(p_q, lnf_g, lnf_b, p_ln, BB * TT);
    k_fillf<<<(BB * TT * HH + 255) / 256, 256>>>(p_acc, BB * TT * HH);
    k_zeroi<<<(BB * VV + 255) / 256, 256>>>(p_cnt, BB * VV);
    k_count<<<BB * EE, 128>>>(p_sel_t, p_cnt, TT, KSEL_T);
    k_moe1<<<dim3(II / 64, (KSEL_T + 63) / 64, BB * EE), 256>>>(
        p_ln, e_w1, e_b1, p_sel_t, p_h, TT, KSEL_T);
    k_moe2<<<dim3(HH / 64, (KSEL_T + 63) / 64, BB * EE), 256>>>(
        p_h, e_w2, e_b2, p_sel_t, p_acc, TT, KSEL_T);
    k_combine<<<(BB * TT * HH + 255) / 256, 256>>>(
        p_q, p_acc, p_cnt, out_q, BB * TT * HH);

    // ---- image-stream MoE (input = raw image tokens) ----
    k_fillf<<<(BB * VV * HH + 255) / 256, 256>>>(p_acc, BB * VV * HH);
    k_zeroi<<<(BB * VV + 255) / 256, 256>>>(p_cnt, BB * VV);
    k_count<<<BB * EE, 128>>>(p_sel_i, p_cnt, VV, KSEL_V);
    k_moe1<<<dim3(II / 64, (KSEL_V + 63) / 64, BB * EE), 256>>>(
        in_img, e_w1, e_b1, p_sel_i, p_h, VV, KSEL_V);
    k_moe2<<<dim3(HH / 64, (KSEL_V + 63) / 64, BB * EE), 256>>>(
        p_h, e_w2, e_b2, p_sel_i, p_acc, VV, KSEL_V);
    k_combine<<<(BB * VV * HH + 255) / 256, 256>>>(
        in_img, p_acc, p_cnt, out_img, BB * VV * HH);
}

// round 3
// speedup vs baseline: 2.6770x; 2.6770x over previous
#include <cuda_runtime.h>
#include <math.h>
#include <stdint.h>

// ---------------- problem constants ----------------
#define BB   4
#define TT   512
#define VV   576
#define LL   256
#define HH   1024
#define NHH  16
#define HDD  64
#define II   4096
#define EE   8
#define KSEL_T 80
#define KSEL_V 90
#define SELCAP 96
#define LN_EPS 1e-5f

// ---------------- scratch ----------------
__device__ float g_ln   [BB*TT*HH];
__device__ float g_q    [BB*TT*HH];
__device__ float g_cq   [BB*TT*HH];
__device__ float g_qkv  [BB*TT*3*HH];
__device__ float g_kv   [BB*VV*2*HH];
__device__ float g_scores[BB*NHH*TT*VV];
__device__ float g_attn [BB*TT*HH];
__device__ float g_h    [BB*EE*SELCAP*II];
__device__ float g_acc  [BB*VV*HH];
__device__ float g_ctx_img[BB*HH];
__device__ float g_ctx_txt[BB*HH];
__device__ float g_gb_img[BB*EE];
__device__ float g_gb_txt[BB*EE];
__device__ float g_probs_t[BB*TT*EE];
__device__ float g_probs_i[BB*VV*EE];
__device__ int   g_sel_t[BB*EE*SELCAP];
__device__ int   g_sel_i[BB*EE*SELCAP];
__device__ int   g_cnt  [BB*VV];

// ---------------- helpers ----------------
__device__ __forceinline__ float gelu_f(float x) {
    float x3 = x * x * x;
    return 0.5f * x * (1.0f + tanhf(0.7978845608028654f * (x + 0.044715f * x3)));
}

__device__ __forceinline__ uint32_t f2tf32(float v) {
    uint32_t r;
    asm("cvt.rna.tf32.f32 %0, %1;" : "=r"(r) : "f"(v));
    return r;
}

__device__ __forceinline__ void mma_tf32(float c[4],
    uint32_t a0, uint32_t a1, uint32_t a2, uint32_t a3,
    uint32_t b0, uint32_t b1)
{
    asm volatile(
        "mma.sync.aligned.m16n8k8.row.col.f32.tf32.tf32.f32 "
        "{%0,%1,%2,%3}, {%4,%5,%6,%7}, {%8,%9}, {%0,%1,%2,%3};"
        : "+f"(c[0]), "+f"(c[1]), "+f"(c[2]), "+f"(c[3])
        : "r"(a0), "r"(a1), "r"(a2), "r"(a3), "r"(b0), "r"(b1));
}

// ---------------- tensor-core GEMM ----------------
// C[M,N] = alpha * A@op(B) + bias + res, epilogues. 128x64x32 tiles, 256 thr.
// TRANSB=true: B is [N,K] row-major. false: B is [K,N] row-major.
#define BM 128
#define BN 64
#define BKS 32

template<bool TRANSB, bool GELU_E, bool ATOMIC>
__device__ __forceinline__ void mma_gemm(
    const float* __restrict__ A, int lda, const int* __restrict__ arow,
    const float* __restrict__ Bp, int ldb,
    const float* __restrict__ bias, const float* __restrict__ res,
    float* __restrict__ C, int ldc, const int* __restrict__ crow,
    int M, int N, int K, float alpha)
{
    __shared__ uint32_t As[BM][BKS + 4];   // [m][k], row pad 36 -> frag loads conflict-free
    __shared__ uint32_t Bs[BKS][BN + 8];   // [k][n], row pad 72

    const int tid  = threadIdx.x;
    const int lane = tid & 31, warp = tid >> 5;
    const int wm = (warp & 3) * 32;
    const int wn = (warp >> 2) * 32;
    const int m0 = blockIdx.y * BM, n0 = blockIdx.x * BN;

    float c[2][4][4];
#pragma unroll
    for (int i = 0; i < 2; i++)
#pragma unroll
        for (int j = 0; j < 4; j++)
#pragma unroll
            for (int q = 0; q < 4; q++) c[i][j][q] = 0.0f;

    const int la_m = tid >> 3, la_c4 = (tid & 7) * 4;    // A: 32 rows/pass, 8 f4/row

    for (int k0 = 0; k0 < K; k0 += BKS) {
        // ---- A tile -> As[m][k] (tf32) ----
#pragma unroll
        for (int p = 0; p < 4; p++) {
            int m = la_m + p * 32;
            int gm = m0 + m;
            float4 v = make_float4(0.f, 0.f, 0.f, 0.f);
            if (gm < M) {
                int row = arow ? arow[gm] : gm;
                v = *(const float4*)&A[(size_t)row * lda + k0 + la_c4];
            }
            uint4 t;
            t.x = f2tf32(v.x); t.y = f2tf32(v.y); t.z = f2tf32(v.z); t.w = f2tf32(v.w);
            *(uint4*)&As[m][la_c4] = t;
        }
        // ---- B tile -> Bs[k][n] (tf32) ----
        if (TRANSB) {
#pragma unroll
            for (int p = 0; p < 2; p++) {
                int n = (tid >> 3) + p * 32;
                int gn = n0 + n;
                float4 v = make_float4(0.f, 0.f, 0.f, 0.f);
                if (gn < N)
                    v = *(const float4*)&Bp[(size_t)gn * ldb + k0 + la_c4];
                Bs[la_c4 + 0][n] = f2tf32(v.x);
                Bs[la_c4 + 1][n] = f2tf32(v.y);
                Bs[la_c4 + 2][n] = f2tf32(v.z);
                Bs[la_c4 + 3][n] = f2tf32(v.w);
            }
        } else {
#pragma unroll
            for (int p = 0; p < 2; p++) {
                int k = (tid >> 4) + p * 16;
                int c4 = (tid & 15) * 4;
                float4 v = make_float4(0.f, 0.f, 0.f, 0.f);
                if (n0 + c4 < N)
                    v = *(const float4*)&Bp[(size_t)(k0 + k) * ldb + n0 + c4];
                uint4 t;
                t.x = f2tf32(v.x); t.y = f2tf32(v.y); t.z = f2tf32(v.z); t.w = f2tf32(v.w);
                *(uint4*)&Bs[k][c4] = t;
            }
        }
        __syncthreads();

        // ---- compute ----
#pragma unroll
        for (int ks = 0; ks < 4; ks++) {
            const int kk = ks * 8;
            uint32_t a[2][4], b[4][2];
#pragma unroll
            for (int i = 0; i < 2; i++) {
                int r = wm + i * 16 + (lane >> 2);
                int cc = kk + (lane & 3);
                a[i][0] = As[r][cc];
                a[i][1] = As[r + 8][cc];
                a[i][2] = As[r][cc + 4];
                a[i][3] = As[r + 8][cc + 4];
            }
#pragma unroll
            for (int j = 0; j < 4; j++) {
                int br = kk + (lane & 3);
                int bc = wn + j * 8 + (lane >> 2);
                b[j][0] = Bs[br][bc];
                b[j][1] = Bs[br + 4][bc];
            }
#pragma unroll
            for (int i = 0; i < 2; i++)
#pragma unroll
                for (int j = 0; j < 4; j++)
                    mma_tf32(c[i][j], a[i][0], a[i][1], a[i][2], a[i][3],
                             b[j][0], b[j][1]);
        }
        __syncthreads();
    }

    // ---- epilogue ----
#pragma unroll
    for (int i = 0; i < 2; i++) {
        int rm = m0 + wm + i * 16 + (lane >> 2);
#pragma unroll
        for (int j = 0; j < 4; j++) {
            int cn = n0 + wn + j * 8 + 2 * (lane & 3);
#pragma unroll
            for (int rr = 0; rr < 2; rr++) {
                int gm = rm + rr * 8;
                if (gm >= M) continue;
                int orow = crow ? crow[gm] : gm;
#pragma unroll
                for (int qq = 0; qq < 2; qq++) {
                    int gn = cn + qq;
                    if (gn >= N) continue;
                    float v = c[i][j][rr * 2 + qq] * alpha;
                    if (bias) v += bias[gn];
                    if (res)  v += res[(size_t)gm * ldc + gn];
                    if (GELU_E) v = gelu_f(v);
                    if (ATOMIC) atomicAdd(&C[(size_t)orow * ldc + gn], v);
                    else        C[(size_t)orow * ldc + gn] = v;
                }
            }
        }
    }
}

// ---------------- GEMM wrappers ----------------
__global__ __launch_bounds__(256) void k_sgemm(
    const float* A, int lda, const float* W, int ldw,
    const float* bias, const float* res,
    float* C, int ldc, int M, int N, int K)
{
    mma_gemm<true, false, false>(A, lda, nullptr, W, ldw, bias, res, C, ldc,
                                 nullptr, M, N, K, 1.0f);
}

__global__ __launch_bounds__(256) void k_scores(
    const float* Q, int qbs, int qld,
    const float* Kp, int kbs, int kld,
    float* S, int Tq, int Skv)
{
    int z = blockIdx.z; int b = z / NHH, h = z % NHH;
    mma_gemm<true, false, false>(
        Q + (size_t)b * qbs + h * HDD, qld, nullptr,
        Kp + (size_t)b * kbs + h * HDD, kld,
        nullptr, nullptr,
        S + (size_t)z * Tq * Skv, Skv, nullptr,
        Tq, Skv, HDD, 0.125f);
}

__global__ __launch_bounds__(256) void k_av(
    const float* P, const float* Vb, int vbs, int vld,
    float* O, int Tq, int Skv)
{
    int z = blockIdx.z; int b = z / NHH, h = z % NHH;
    mma_gemm<false, false, false>(
        P + (size_t)z * Tq * Skv, Skv, nullptr,
        Vb + (size_t)b * vbs + h * HDD, vld,
        nullptr, nullptr,
        O + (size_t)b * Tq * HH + h * HDD, HH, nullptr,
        Tq, HDD, Skv, 1.0f);
}

__global__ __launch_bounds__(256) void k_moe1(
    const float* X, const float* w1, const float* b1, const int* sel,
    float* Hb, int S, int ksel)
{
    int g = blockIdx.z, b = g / EE, e = g % EE;
    mma_gemm<true, true, false>(
        X + (size_t)b * S * HH, HH, sel + g * SELCAP,
        w1 + (size_t)e * II * HH, HH, b1 + (size_t)e * II, nullptr,
        Hb + (size_t)g * SELCAP * II, II, nullptr,
        ksel, II, HH, 1.0f);
}

__global__ __launch_bounds__(256) void k_moe2(
    const float* Hb, const float* w2, const float* b2, const int* sel,
    float* Acc, int S, int ksel)
{
    int g = blockIdx.z, b = g / EE, e = g % EE;
    mma_gemm<true, false, true>(
        Hb + (size_t)g * SELCAP * II, II, nullptr,
        w2 + (size_t)e * HH * II, II, b2 + (size_t)e * HH, nullptr,
        Acc + (size_t)b * S * HH, HH, sel + g * SELCAP,
        ksel, HH, II, 1.0f);
}

// ---------------- layernorm ----------------
__global__ void k_ln(const float* X, const float* gg, const float* bb,
                     float* Y, int rows)
{
    int r = blockIdx.x;
    const float* x = X + (size_t)r * HH;
    float* y = Y + (size_t)r * HH;
    int tid = threadIdx.x;
    float s = 0.0f, s2 = 0.0f;
    for (int i = tid; i < HH; i += 256) { float v = x[i]; s += v; s2 += v * v; }
    __shared__ float r1[256], r2[256];
    r1[tid] = s; r2[tid] = s2; __syncthreads();
    for (int st = 128; st; st >>= 1) {
        if (tid < st) { r1[tid] += r1[tid + st]; r2[tid] += r2[tid + st]; }
        __syncthreads();
    }
    float mean = r1[0] * (1.0f / HH);
    float var  = r2[0] * (1.0f / HH) - mean * mean;
    float rstd = rsqrtf(var + LN_EPS);
    for (int i = tid; i < HH; i += 256)
        y[i] = (x[i] - mean) * rstd * gg[i] + bb[i];
}

// ---------------- softmax: warp per row, register resident ----------------
template<int W>
__global__ __launch_bounds__(256) void k_softmax_w(float* __restrict__ S)
{
    const int row = blockIdx.x * 8 + (threadIdx.x >> 5);
    const int lane = threadIdx.x & 31;
    float* r = S + (size_t)row * W;
    constexpr int NV = W / 32;
    float v[NV];
    float m = -3.0e38f;
#pragma unroll
    for (int j = 0; j < NV; j++) { v[j] = r[lane + (j << 5)]; m = fmaxf(m, v[j]); }
#pragma unroll
    for (int o = 16; o; o >>= 1) m = fmaxf(m, __shfl_xor_sync(0xffffffffu, m, o));
    float s = 0.0f;
#pragma unroll
    for (int j = 0; j < NV; j++) { v[j] = expf(v[j] - m); s += v[j]; }
#pragma unroll
    for (int o = 16; o; o >>= 1) s += __shfl_xor_sync(0xffffffffu, s, o);
    float inv = 1.0f / s;
#pragma unroll
    for (int j = 0; j < NV; j++) r[lane + (j << 5)] = v[j] * inv;
}

// ---------------- gating / misc ----------------
__global__ void k_mean(const float* X, float* ctx, int S)
{
    int b = blockIdx.x;
    for (int c = threadIdx.x; c < HH; c += blockDim.x) {
        float s = 0.0f;
        for (int j = 0; j < S; j++) s += X[(size_t)(b * S + j) * HH + c];
        ctx[b * HH + c] = s / (float)S;
    }
}

__global__ void k_ctxbias(const float* ctx, const float* gw, const float* gb,
                          float* outp)
{
    int g = blockIdx.x; int b = g / EE, e = g % EE;
    int tid = threadIdx.x;
    float s = 0.0f;
    for (int c = tid; c < HH; c += 256)
        s += ctx[b * HH + c] * gw[(size_t)e * 2 * HH + HH + c];
    __shared__ float red[256];
    red[tid] = s; __syncthreads();
    for (int st = 128; st; st >>= 1) {
        if (tid < st) red[tid] += red[tid + st];
        __syncthreads();
    }
    if (tid == 0) outp[g] = red[0] + gb[e];
}

__global__ void k_gate(const float* X, const float* gw, const float* cb,
                       float* probs, int S)
{
    int t = blockIdx.x; int b = t / S;
    const float* x = X + (size_t)t * HH;
    int tid = threadIdx.x;
    float part[EE];
#pragma unroll
    for (int e = 0; e < EE; e++) part[e] = 0.0f;
    for (int c = tid; c < HH; c += 256) {
        float xv = x[c];
#pragma unroll
        for (int e = 0; e < EE; e++) part[e] += xv * gw[(size_t)e * 2 * HH + c];
    }
    __shared__ float red[256];
    __shared__ float lg[EE];
    for (int e = 0; e < EE; e++) {
        red[tid] = part[e]; __syncthreads();
        for (int st = 128; st; st >>= 1) {
            if (tid < st) red[tid] += red[tid + st];
            __syncthreads();
        }
        if (tid == 0) lg[e] = red[0] + cb[b * EE + e];
        __syncthreads();
    }
    if (tid == 0) {
        float mx = lg[0];
#pragma unroll
        for (int e = 1; e < EE; e++) mx = fmaxf(mx, lg[e]);
        float sum = 0.0f, ex[EE];
#pragma unroll
        for (int e = 0; e < EE; e++) { ex[e] = expf(lg[e] - mx); sum += ex[e]; }
        float inv = 1.0f / sum;
#pragma unroll
        for (int e = 0; e < EE; e++) probs[(size_t)t * EE + e] = ex[e] * inv;
    }
}

__global__ void k_topk(const float* probs, int S, int ksel, int* sel)
{
    int g = blockIdx.x; int b = g / EE, e = g % EE;
    int tid = threadIdx.x;
    __shared__ float v[VV];
    __shared__ float bestv[256];
    __shared__ int   besti[256];
    for (int i = tid; i < S; i += 256) v[i] = probs[(size_t)(b * S + i) * EE + e];
    __syncthreads();
    for (int it = 0; it < ksel; it++) {
        float bv = -3.0e38f; int bi = S;
        for (int i = tid; i < S; i += 256) {
            float x = v[i];
            if (x > bv || (x == bv && i < bi)) { bv = x; bi = i; }
        }
        bestv[tid] = bv; besti[tid] = bi; __syncthreads();
        for (int st = 128; st; st >>= 1) {
            if (tid < st) {
                if (bestv[tid + st] > bestv[tid] ||
                    (bestv[tid + st] == bestv[tid] && besti[tid + st] < besti[tid])) {
                    bestv[tid] = bestv[tid + st];
                    besti[tid] = besti[tid + st];
                }
            }
            __syncthreads();
        }
        if (tid == 0) { sel[g * SELCAP + it] = besti[0]; v[besti[0]] = -1.0e30f; }
        __syncthreads();
    }
}

__global__ void k_count(const int* sel, int* cnt, int S, int ksel)
{
    int g = blockIdx.x; int b = g / EE;
    for (int j = threadIdx.x; j < ksel; j += blockDim.x)
        atomicAdd(&cnt[b * S + sel[g * SELCAP + j]], 1);
}

__global__ void k_combine(const float* base, const float* acc, const int* cnt,
                          float* outp, int n)
{
    int i = blockIdx.x * 256 + threadIdx.x;
    if (i < n) {
        int tok = i / HH;
        outp[i] = base[i] + acc[i] / fmaxf((float)cnt[tok], 1.0f);
    }
}

__global__ void k_fillf(float* p, int n)
{
    int i = blockIdx.x * 256 + threadIdx.x;
    if (i < n) p[i] = 0.0f;
}

__global__ void k_zeroi(int* p, int n)
{
    int i = blockIdx.x * 256 + threadIdx.x;
    if (i < n) p[i] = 0;
}

// ---------------- launch ----------------
extern "C" void kernel_launch(void* const* d_in, const int* in_sizes, int n_in,
                              void* d_out, int out_size)
{
    (void)in_sizes; (void)n_in; (void)out_size;
    const float* in_q      = (const float*)d_in[0];
    const float* in_img    = (const float*)d_in[1];
    const float* in_txt    = (const float*)d_in[2];
    const float* sa_w_in   = (const float*)d_in[3];
    const float* sa_b_in   = (const float*)d_in[4];
    const float* sa_w_out  = (const float*)d_in[5];
    const float* sa_b_out  = (const float*)d_in[6];
    const float* ca_w_in   = (const float*)d_in[7];
    const float* ca_b_in   = (const float*)d_in[8];
    const float* ca_w_out  = (const float*)d_in[9];
    const float* ca_b_out  = (const float*)d_in[10];
    const float* gate_img_w= (const float*)d_in[11];
    const float* gate_img_b= (const float*)d_in[12];
    const float* gate_txt_w= (const float*)d_in[13];
    const float* gate_txt_b= (const float*)d_in[14];
    const float* e_w1      = (const float*)d_in[15];
    const float* e_b1      = (const float*)d_in[16];
    const float* e_w2      = (const float*)d_in[17];
    const float* e_b2      = (const float*)d_in[18];
    const float* lnq_g     = (const float*)d_in[19];
    const float* lnq_b     = (const float*)d_in[20];
    const float* lnc_g     = (const float*)d_in[21];
    const float* lnc_b     = (const float*)d_in[22];
    const float* lnf_g     = (const float*)d_in[23];
    const float* lnf_b     = (const float*)d_in[24];
    float* out_q   = (float*)d_out;
    float* out_img = out_q + (size_t)BB * TT * HH;

    float *p_ln, *p_q, *p_cq, *p_qkv, *p_kv, *p_scores, *p_attn, *p_h, *p_acc;
    float *p_ctx_img, *p_ctx_txt, *p_gb_img, *p_gb_txt, *p_probs_t, *p_probs_i;
    int *p_sel_t, *p_sel_i, *p_cnt;
    cudaGetSymbolAddress((void**)&p_ln, g_ln);
    cudaGetSymbolAddress((void**)&p_q, g_q);
    cudaGetSymbolAddress((void**)&p_cq, g_cq);
    cudaGetSymbolAddress((void**)&p_qkv, g_qkv);
    cudaGetSymbolAddress((void**)&p_kv, g_kv);
    cudaGetSymbolAddress((void**)&p_scores, g_scores);
    cudaGetSymbolAddress((void**)&p_attn, g_attn);
    cudaGetSymbolAddress((void**)&p_h, g_h);
    cudaGetSymbolAddress((void**)&p_acc, g_acc);
    cudaGetSymbolAddress((void**)&p_ctx_img, g_ctx_img);
    cudaGetSymbolAddress((void**)&p_ctx_txt, g_ctx_txt);
    cudaGetSymbolAddress((void**)&p_gb_img, g_gb_img);
    cudaGetSymbolAddress((void**)&p_gb_txt, g_gb_txt);
    cudaGetSymbolAddress((void**)&p_probs_t, g_probs_t);
    cudaGetSymbolAddress((void**)&p_probs_i, g_probs_i);
    cudaGetSymbolAddress((void**)&p_sel_t, g_sel_t);
    cudaGetSymbolAddress((void**)&p_sel_i, g_sel_i);
    cudaGetSymbolAddress((void**)&p_cnt, g_cnt);

    // ---- self attention ----
    k_ln<<<BB * TT, 256>>>(in_q, lnq_g, lnq_b, p_ln, BB * TT);
    k_sgemm<<<dim3(3 * HH / BN, BB * TT / BM), 256>>>(
        p_ln, HH, sa_w_in, HH, sa_b_in, nullptr, p_qkv, 3 * HH,
        BB * TT, 3 * HH, HH);
    k_scores<<<dim3(TT / BN, TT / BM, BB * NHH), 256>>>(
        p_qkv, TT * 3 * HH, 3 * HH, p_qkv + HH, TT * 3 * HH, 3 * HH,
        p_scores, TT, TT);
    k_softmax_w<TT><<<BB * NHH * TT / 8, 256>>>(p_scores);
    k_av<<<dim3(1, TT / BM, BB * NHH), 256>>>(
        p_scores, p_qkv + 2 * HH, TT * 3 * HH, 3 * HH, p_attn, TT, TT);
    k_sgemm<<<dim3(HH / BN, BB * TT / BM), 256>>>(
        p_attn, HH, sa_w_out, HH, sa_b_out, in_q, p_q, HH, BB * TT, HH, HH);

    // ---- cross attention ----
    k_ln<<<BB * TT, 256>>>(p_q, lnc_g, lnc_b, p_ln, BB * TT);
    k_sgemm<<<dim3(HH / BN, BB * TT / BM), 256>>>(
        p_ln, HH, ca_w_in, HH, ca_b_in, nullptr, p_cq, HH, BB * TT, HH, HH);
    k_sgemm<<<dim3(2 * HH / BN, (BB * VV + BM - 1) / BM), 256>>>(
        in_img, HH, ca_w_in + (size_t)HH * HH, HH, ca_b_in + HH, nullptr,
        p_kv, 2 * HH, BB * VV, 2 * HH, HH);
    k_scores<<<dim3(VV / BN, TT / BM, BB * NHH), 256>>>(
        p_cq, TT * HH, HH, p_kv, VV * 2 * HH, 2 * HH, p_scores, TT, VV);
    k_softmax_w<VV><<<BB * NHH * TT / 8, 256>>>(p_scores);
    k_av<<<dim3(1, TT / BM, BB * NHH), 256>>>(
        p_scores, p_kv + HH, VV * 2 * HH, 2 * HH, p_attn, TT, VV);
    k_sgemm<<<dim3(HH / BN, BB * TT / BM), 256>>>(
        p_attn, HH, ca_w_out, HH, ca_b_out, p_q, p_q, HH, BB * TT, HH, HH);

    // ---- gating ----
    k_mean<<<BB, 256>>>(in_img, p_ctx_img, VV);
    k_mean<<<BB, 256>>>(in_txt, p_ctx_txt, LL);
    k_ctxbias<<<BB * EE, 256>>>(p_ctx_txt, gate_img_w, gate_img_b, p_gb_img);
    k_ctxbias<<<BB * EE, 256>>>(p_ctx_img, gate_txt_w, gate_txt_b, p_gb_txt);
    k_gate<<<BB * VV, 256>>>(in_img, gate_img_w, p_gb_img, p_probs_i, VV);
    k_gate<<<BB * TT, 256>>>(p_q, gate_txt_w, p_gb_txt, p_probs_t, TT);
    k_topk<<<BB * EE, 256>>>(p_probs_t, TT, KSEL_T, p_sel_t);
    k_topk<<<BB * EE, 256>>>(p_probs_i, VV, KSEL_V, p_sel_i);

    // ---- text-stream MoE ----
    k_ln<<<BB * TT, 256>>>(p_q, lnf_g, lnf_b, p_ln, BB * TT);
    k_fillf<<<(BB * TT * HH + 255) / 256, 256>>>(p_acc, BB * TT * HH);
    k_zeroi<<<(BB * VV + 255) / 256, 256>>>(p_cnt, BB * VV);
    k_count<<<BB * EE, 128>>>(p_sel_t, p_cnt, TT, KSEL_T);
    k_moe1<<<dim3(II / BN, 1, BB * EE), 256>>>(
        p_ln, e_w1, e_b1, p_sel_t, p_h, TT, KSEL_T);
    k_moe2<<<dim3(HH / BN, 1, BB * EE), 256>>>(
        p_h, e_w2, e_b2, p_sel_t, p_acc, TT, KSEL_T);
    k_combine<<<(BB * TT * HH + 255) / 256, 256>>>(
        p_q, p_acc, p_cnt, out_q, BB * TT * HH);

    // ---- image-stream MoE ----
    k_fillf<<<(BB * VV * HH + 255) / 256, 256>>>(p_acc, BB * VV * HH);
    k_zeroi<<<(BB * VV + 255) / 256, 256>>>(p_cnt, BB * VV);
    k_count<<<BB * EE, 128>>>(p_sel_i, p_cnt, VV, KSEL_V);
    k_moe1<<<dim3(II / BN, 1, BB * EE), 256>>>(
        in_img, e_w1, e_b1, p_sel_i, p_h, VV, KSEL_V);
    k_moe2<<<dim3(HH / BN, 1, BB * EE), 256>>>(
        p_h, e_w2, e_b2, p_sel_i, p_acc, VV, KSEL_V);
    k_combine<<<(BB * VV * HH + 255) / 256, 256>>>(
        in_img, p_acc, p_cnt, out_img, BB * VV * HH);
}

// round 4
// speedup vs baseline: 4.5938x; 1.7160x over previous
#include <cuda_runtime.h>
#include <math.h>
#include <stdint.h>

// ---------------- problem constants ----------------
#define BB   4
#define TT   512
#define VV   576
#define LL   256
#define HH   1024
#define NHH  16
#define HDD  64
#define II   4096
#define EE   8
#define KSEL_T 80
#define KSEL_V 90
#define SELCAP 96
#define LN_EPS 1e-5f

#define BM 128
#define BKW 32          // K per tile (floats)

// ---------------- scratch ----------------
__device__ float g_ln   [BB*TT*HH];
__device__ float g_q    [BB*TT*HH];
__device__ float g_cq   [BB*TT*HH];
__device__ float g_qkv  [BB*TT*3*HH];
__device__ float g_kv   [BB*VV*2*HH];
__device__ float g_scores[BB*NHH*TT*VV];
__device__ float g_attn [BB*TT*HH];
__device__ float g_vt   [BB*NHH*HDD*VV];
__device__ float g_h    [BB*EE*SELCAP*II];
__device__ float g_acc  [BB*VV*HH];
__device__ float g_ctx_img[BB*HH];
__device__ float g_ctx_txt[BB*HH];
__device__ float g_gb_img[BB*EE];
__device__ float g_gb_txt[BB*EE];
__device__ float g_probs_t[BB*TT*EE];
__device__ float g_probs_i[BB*VV*EE];
__device__ int   g_sel_t[BB*EE*SELCAP];
__device__ int   g_sel_i[BB*EE*SELCAP];
__device__ int   g_cnt  [BB*VV];

// ---------------- helpers ----------------
__device__ __forceinline__ float gelu_f(float x) {
    float x3 = x * x * x;
    return 0.5f * x * (1.0f + tanhf(0.7978845608028654f * (x + 0.044715f * x3)));
}
__device__ __forceinline__ uint32_t f2tf32(float v) {
    uint32_t r;
    asm("cvt.rna.tf32.f32 %0, %1;" : "=r"(r) : "f"(v));
    return r;
}
__device__ __forceinline__ float roundtf(float v) {
    return __uint_as_float(f2tf32(v));
}
__device__ __forceinline__ void mma_tf32(float c[4],
    uint32_t a0, uint32_t a1, uint32_t a2, uint32_t a3,
    uint32_t b0, uint32_t b1)
{
    asm volatile(
        "mma.sync.aligned.m16n8k8.row.col.f32.tf32.tf32.f32 "
        "{%0,%1,%2,%3}, {%4,%5,%6,%7}, {%8,%9}, {%0,%1,%2,%3};"
        : "+f"(c[0]), "+f"(c[1]), "+f"(c[2]), "+f"(c[3])
        : "r"(a0), "r"(a1), "r"(a2), "r"(a3), "r"(b0), "r"(b1));
}
__device__ __forceinline__ void cpa16(float* dst, const float* src, bool valid) {
    uint32_t d = (uint32_t)__cvta_generic_to_shared(dst);
    asm volatile("cp.async.cg.shared.global [%0], [%1], 16, %2;"
                 :: "r"(d), "l"(src), "r"(valid ? 16 : 0));
}

// ---------------- tensor-core GEMM (all layouts: C = alpha*A@B^T + eps) ----
// A [M,K] row-major (optional row gather), B [N,K] row-major.
// Double-buffered cp.async, 128xBN x32 tiles, 256 threads.
template<int BN, bool GELU_E, bool ATOMIC, bool ROUND>
__device__ __forceinline__ void mma_gemm(
    float* smem,
    const float* __restrict__ A, int lda, const int* __restrict__ arow,
    const float* __restrict__ Bp, int ldb,
    const float* __restrict__ bias, const float* __restrict__ res,
    float* __restrict__ C, int ldc, const int* __restrict__ crow,
    int M, int N, int K, float alpha)
{
    constexpr int NJ  = BN / 16;        // n8-frags per warp
    constexpr int ASZ = BM * 36;
    constexpr int BSZ = BN * 36;
    float* Asb[2] = { smem, smem + ASZ };
    float* Bsb[2] = { smem + 2 * ASZ, smem + 2 * ASZ + BSZ };

    const int tid  = threadIdx.x;
    const int lane = tid & 31, warp = tid >> 5;
    const int wm = (warp & 3) * 32;
    const int wn = (warp >> 2) * (BN / 2);
    const int m0 = blockIdx.y * BM, n0 = blockIdx.x * BN;

    // per-thread load geometry (fixed across K)
    const int sr = tid >> 3;            // 0..31 row-in-pass
    const int kc = (tid & 7) * 4;       // float offset in K (16B)
    int rowA[4];
#pragma unroll
    for (int p = 0; p < 4; p++) {
        int gm = m0 + sr + p * 32;
        rowA[p] = (gm < M) ? (arow ? arow[gm] : gm) : -1;
    }
    int rowB[BN / 32];
#pragma unroll
    for (int p = 0; p < BN / 32; p++) {
        int gn = n0 + sr + p * 32;
        rowB[p] = (gn < N) ? gn : -1;
    }

    float c[2][NJ][4];
#pragma unroll
    for (int i = 0; i < 2; i++)
#pragma unroll
        for (int j = 0; j < NJ; j++)
#pragma unroll
            for (int q = 0; q < 4; q++) c[i][j][q] = 0.0f;

    const int KT = K / BKW;

    // prologue: load tile 0 into buffer 0
    {
#pragma unroll
        for (int p = 0; p < 4; p++)
            cpa16(Asb[0] + (sr + p * 32) * 36 + kc,
                  A + (size_t)(rowA[p] < 0 ? 0 : rowA[p]) * lda + kc, rowA[p] >= 0);
#pragma unroll
        for (int p = 0; p < BN / 32; p++)
            cpa16(Bsb[0] + (sr + p * 32) * 36 + kc,
                  Bp + (size_t)(rowB[p] < 0 ? 0 : rowB[p]) * ldb + kc, rowB[p] >= 0);
    }
    asm volatile("cp.async.commit_group;");

    for (int kt = 0; kt < KT; kt++) {
        const int cur = kt & 1;
        if (kt + 1 < KT) {
            const int k0 = (kt + 1) * BKW;
#pragma unroll
            for (int p = 0; p < 4; p++)
                cpa16(Asb[cur ^ 1] + (sr + p * 32) * 36 + kc,
                      A + (size_t)(rowA[p] < 0 ? 0 : rowA[p]) * lda + k0 + kc,
                      rowA[p] >= 0);
#pragma unroll
            for (int p = 0; p < BN / 32; p++)
                cpa16(Bsb[cur ^ 1] + (sr + p * 32) * 36 + kc,
                      Bp + (size_t)(rowB[p] < 0 ? 0 : rowB[p]) * ldb + k0 + kc,
                      rowB[p] >= 0);
        }
        asm volatile("cp.async.commit_group;");
        asm volatile("cp.async.wait_group 1;");
        __syncthreads();

        const float* Ab = Asb[cur];
        const float* Bb = Bsb[cur];
#pragma unroll
        for (int ks = 0; ks < 4; ks++) {
            const int cc = ks * 8 + (lane & 3);
            uint32_t a[2][4];
#pragma unroll
            for (int i = 0; i < 2; i++) {
                const int r = wm + i * 16 + (lane >> 2);
                a[i][0] = __float_as_uint(Ab[r * 36 + cc]);
                a[i][1] = __float_as_uint(Ab[(r + 8) * 36 + cc]);
                a[i][2] = __float_as_uint(Ab[r * 36 + cc + 4]);
                a[i][3] = __float_as_uint(Ab[(r + 8) * 36 + cc + 4]);
            }
            uint32_t b[NJ][2];
#pragma unroll
            for (int j = 0; j < NJ; j++) {
                const int bc = wn + j * 8 + (lane >> 2);
                b[j][0] = __float_as_uint(Bb[bc * 36 + cc]);
                b[j][1] = __float_as_uint(Bb[bc * 36 + cc + 4]);
            }
#pragma unroll
            for (int i = 0; i < 2; i++)
#pragma unroll
                for (int j = 0; j < NJ; j++)
                    mma_tf32(c[i][j], a[i][0], a[i][1], a[i][2], a[i][3],
                             b[j][0], b[j][1]);
        }
        __syncthreads();
    }

    // epilogue
#pragma unroll
    for (int i = 0; i < 2; i++) {
        int rm = m0 + wm + i * 16 + (lane >> 2);
#pragma unroll
        for (int j = 0; j < NJ; j++) {
            int cn = n0 + wn + j * 8 + 2 * (lane & 3);
#pragma unroll
            for (int rr = 0; rr < 2; rr++) {
                int gm = rm + rr * 8;
                if (gm >= M) continue;
                int orow = crow ? crow[gm] : gm;
#pragma unroll
                for (int qq = 0; qq < 2; qq++) {
                    int gn = cn + qq;
                    if (gn >= N) continue;
                    float v = c[i][j][rr * 2 + qq] * alpha;
                    if (bias) v += bias[gn];
                    if (res)  v += res[(size_t)gm * ldc + gn];
                    if (GELU_E) v = gelu_f(v);
                    if (ROUND)  v = roundtf(v);
                    if (ATOMIC) atomicAdd(&C[(size_t)orow * ldc + gn], v);
                    else        C[(size_t)orow * ldc + gn] = v;
                }
            }
        }
    }
}

// ---------------- GEMM wrappers ----------------
__global__ __launch_bounds__(256) void k_gemm_r(      // bias, optional res, rounded out
    const float* A, int lda, const float* W, int ldw,
    const float* bias, const float* res,
    float* C, int ldc, int M, int N, int K)
{
    extern __shared__ float sm[];
    mma_gemm<128, false, false, true>(sm, A, lda, nullptr, W, ldw, bias, res,
                                      C, ldc, nullptr, M, N, K, 1.0f);
}

__global__ __launch_bounds__(256) void k_gemm_p(      // bias+res, full precision out
    const float* A, int lda, const float* W, int ldw,
    const float* bias, const float* res,
    float* C, int ldc, int M, int N, int K)
{
    extern __shared__ float sm[];
    mma_gemm<128, false, false, false>(sm, A, lda, nullptr, W, ldw, bias, res,
                                       C, ldc, nullptr, M, N, K, 1.0f);
}

__global__ __launch_bounds__(256) void k_scores(
    const float* Q, int qbs, int qld,
    const float* Kp, int kbs, int kld,
    float* S, int Tq, int Skv)
{
    extern __shared__ float sm[];
    int z = blockIdx.z; int b = z / NHH, h = z % NHH;
    mma_gemm<128, false, false, false>(sm,
        Q + (size_t)b * qbs + h * HDD, qld, nullptr,
        Kp + (size_t)b * kbs + h * HDD, kld,
        nullptr, nullptr,
        S + (size_t)z * Tq * Skv, Skv, nullptr,
        Tq, Skv, HDD, 0.125f);
}

__global__ __launch_bounds__(256) void k_av(
    const float* P, const float* Vt, float* O, int Tq, int Skv)
{
    extern __shared__ float sm[];
    int z = blockIdx.z; int b = z / NHH, h = z % NHH;
    mma_gemm<64, false, false, true>(sm,
        P + (size_t)z * Tq * Skv, Skv, nullptr,
        Vt + (size_t)z * HDD * Skv, Skv,
        nullptr, nullptr,
        O + (size_t)b * Tq * HH + h * HDD, HH, nullptr,
        Tq, HDD, Skv, 1.0f);
}

__global__ __launch_bounds__(256) void k_moe1(
    const float* X, const float* w1, const float* b1, const int* sel,
    float* Hb, int S, int ksel)
{
    extern __shared__ float sm[];
    int g = blockIdx.z, b = g / EE, e = g % EE;
    mma_gemm<128, true, false, true>(sm,
        X + (size_t)b * S * HH, HH, sel + g * SELCAP,
        w1 + (size_t)e * II * HH, HH, b1 + (size_t)e * II, nullptr,
        Hb + (size_t)g * SELCAP * II, II, nullptr,
        ksel, II, HH, 1.0f);
}

__global__ __launch_bounds__(256) void k_moe2(
    const float* Hb, const float* w2, const float* b2, const int* sel,
    float* Acc, int S, int ksel)
{
    extern __shared__ float sm[];
    int g = blockIdx.z, b = g / EE, e = g % EE;
    mma_gemm<128, false, true, false>(sm,
        Hb + (size_t)g * SELCAP * II, II, nullptr,
        w2 + (size_t)e * HH * II, II, b2 + (size_t)e * HH, nullptr,
        Acc + (size_t)b * S * HH, HH, sel + g * SELCAP,
        ksel, HH, II, 1.0f);
}

// ---------------- V transpose: [S,64] head-slices -> [64,S] ----------------
__global__ void k_transp(const float* __restrict__ X, int ldx,
                         float* __restrict__ Y, int S)
{
    __shared__ float t[32][33];
    int z = blockIdx.z; int b = z >> 4, h = z & 15;
    int t0 = blockIdx.x * 32, d0 = blockIdx.y * 32;
    const float* src = X + ((size_t)b * S) * ldx + h * HDD;
#pragma unroll
    for (int k2 = 0; k2 < 4; k2++) {
        int tt = t0 + threadIdx.y + k2 * 8;
        t[threadIdx.y + k2 * 8][threadIdx.x] =
            src[(size_t)tt * ldx + d0 + threadIdx.x];
    }
    __syncthreads();
    float* dst = Y + ((size_t)z * HDD) * S;
#pragma unroll
    for (int k2 = 0; k2 < 4; k2++) {
        int d = d0 + threadIdx.y + k2 * 8;
        dst[(size_t)d * S + t0 + threadIdx.x] = t[threadIdx.x][threadIdx.y + k2 * 8];
    }
}

// ---------------- layernorm (tf32-rounded output) ----------------
__global__ void k_ln(const float* X, const float* gg, const float* bb,
                     float* Y, int rows)
{
    int r = blockIdx.x;
    const float* x = X + (size_t)r * HH;
    float* y = Y + (size_t)r * HH;
    int tid = threadIdx.x;
    float s = 0.0f, s2 = 0.0f;
    for (int i = tid; i < HH; i += 256) { float v = x[i]; s += v; s2 += v * v; }
    __shared__ float r1[256], r2[256];
    r1[tid] = s; r2[tid] = s2; __syncthreads();
    for (int st = 128; st; st >>= 1) {
        if (tid < st) { r1[tid] += r1[tid + st]; r2[tid] += r2[tid + st]; }
        __syncthreads();
    }
    float mean = r1[0] * (1.0f / HH);
    float var  = r2[0] * (1.0f / HH) - mean * mean;
    float rstd = rsqrtf(var + LN_EPS);
    for (int i = tid; i < HH; i += 256)
        y[i] = roundtf((x[i] - mean) * rstd * gg[i] + bb[i]);
}

// ---------------- softmax: warp per row ----------------
template<int W>
__global__ __launch_bounds__(256) void k_softmax_w(float* __restrict__ S)
{
    const int row = blockIdx.x * 8 + (threadIdx.x >> 5);
    const int lane = threadIdx.x & 31;
    float* r = S + (size_t)row * W;
    constexpr int NV = W / 32;
    float v[NV];
    float m = -3.0e38f;
#pragma unroll
    for (int j = 0; j < NV; j++) { v[j] = r[lane + (j << 5)]; m = fmaxf(m, v[j]); }
#pragma unroll
    for (int o = 16; o; o >>= 1) m = fmaxf(m, __shfl_xor_sync(0xffffffffu, m, o));
    float s = 0.0f;
#pragma unroll
    for (int j = 0; j < NV; j++) { v[j] = expf(v[j] - m); s += v[j]; }
#pragma unroll
    for (int o = 16; o; o >>= 1) s += __shfl_xor_sync(0xffffffffu, s, o);
    float inv = 1.0f / s;
#pragma unroll
    for (int j = 0; j < NV; j++) r[lane + (j << 5)] = roundtf(v[j] * inv);
}

// ---------------- gating / misc ----------------
__global__ void k_mean(const float* X, float* ctx, int S)
{
    int b = blockIdx.y;
    int c = blockIdx.x * 256 + threadIdx.x;
    float s = 0.0f;
    for (int j = 0; j < S; j++) s += X[(size_t)(b * S + j) * HH + c];
    ctx[b * HH + c] = s / (float)S;
}

__global__ void k_ctxbias(const float* ctx, const float* gw, const float* gb,
                          float* outp)
{
    int g = blockIdx.x; int b = g / EE, e = g % EE;
    int tid = threadIdx.x;
    float s = 0.0f;
    for (int c = tid; c < HH; c += 256)
        s += ctx[b * HH + c] * gw[(size_t)e * 2 * HH + HH + c];
    __shared__ float red[256];
    red[tid] = s; __syncthreads();
    for (int st = 128; st; st >>= 1) {
        if (tid < st) red[tid] += red[tid + st];
        __syncthreads();
    }
    if (tid == 0) outp[g] = red[0] + gb[e];
}

__global__ void k_gate(const float* X, const float* gw, const float* cb,
                       float* probs, int S)
{
    int t = blockIdx.x; int b = t / S;
    const float* x = X + (size_t)t * HH;
    int tid = threadIdx.x;
    float part[EE];
#pragma unroll
    for (int e = 0; e < EE; e++) part[e] = 0.0f;
    for (int c = tid; c < HH; c += 256) {
        float xv = x[c];
#pragma unroll
        for (int e = 0; e < EE; e++) part[e] += xv * gw[(size_t)e * 2 * HH + c];
    }
    __shared__ float red[256];
    __shared__ float lg[EE];
    for (int e = 0; e < EE; e++) {
        red[tid] = part[e]; __syncthreads();
        for (int st = 128; st; st >>= 1) {
            if (tid < st) red[tid] += red[tid + st];
            __syncthreads();
        }
        if (tid == 0) lg[e] = red[0] + cb[b * EE + e];
        __syncthreads();
    }
    if (tid == 0) {
        float mx = lg[0];
#pragma unroll
        for (int e = 1; e < EE; e++) mx = fmaxf(mx, lg[e]);
        float sum = 0.0f, ex[EE];
#pragma unroll
        for (int e = 0; e < EE; e++) { ex[e] = expf(lg[e] - mx); sum += ex[e]; }
        float inv = 1.0f / sum;
#pragma unroll
        for (int e = 0; e < EE; e++) probs[(size_t)t * EE + e] = ex[e] * inv;
    }
}

__global__ void k_topk(const float* probs, int S, int ksel, int* sel)
{
    int g = blockIdx.x; int b = g / EE, e = g % EE;
    int tid = threadIdx.x;
    __shared__ float v[VV];
    __shared__ float bestv[256];
    __shared__ int   besti[256];
    for (int i = tid; i < S; i += 256) v[i] = probs[(size_t)(b * S + i) * EE + e];
    __syncthreads();
    for (int it = 0; it < ksel; it++) {
        float bv = -3.0e38f; int bi = S;
        for (int i = tid; i < S; i += 256) {
            float x = v[i];
            if (x > bv || (x == bv && i < bi)) { bv = x; bi = i; }
        }
        bestv[tid] = bv; besti[tid] = bi; __syncthreads();
        for (int st = 128; st; st >>= 1) {
            if (tid < st) {
                if (bestv[tid + st] > bestv[tid] ||
                    (bestv[tid + st] == bestv[tid] && besti[tid + st] < besti[tid])) {
                    bestv[tid] = bestv[tid + st];
                    besti[tid] = besti[tid + st];
                }
            }
            __syncthreads();
        }
        if (tid == 0) { sel[g * SELCAP + it] = besti[0]; v[besti[0]] = -1.0e30f; }
        __syncthreads();
    }
}

__global__ void k_count(const int* sel, int* cnt, int S, int ksel)
{
    int g = blockIdx.x; int b = g / EE;
    for (int j = threadIdx.x; j < ksel; j += blockDim.x)
        atomicAdd(&cnt[b * S + sel[g * SELCAP + j]], 1);
}

__global__ void k_combine(const float* base, const float* acc, const int* cnt,
                          float* outp, int n)
{
    int i = blockIdx.x * 256 + threadIdx.x;
    if (i < n) {
        int tok = i / HH;
        outp[i] = base[i] + acc[i] / fmaxf((float)cnt[tok], 1.0f);
    }
}

__global__ void k_fillf(float* p, int n)
{
    int i = blockIdx.x * 256 + threadIdx.x;
    if (i < n) p[i] = 0.0f;
}

__global__ void k_zeroi(int* p, int n)
{
    int i = blockIdx.x * 256 + threadIdx.x;
    if (i < n) p[i] = 0;
}

// ---------------- launch ----------------
#define SMEM128 ((2*BM*36 + 2*128*36) * 4)
#define SMEM64  ((2*BM*36 + 2*64*36) * 4)

extern "C" void kernel_launch(void* const* d_in, const int* in_sizes, int n_in,
                              void* d_out, int out_size)
{
    (void)in_sizes; (void)n_in; (void)out_size;
    const float* in_q      = (const float*)d_in[0];
    const float* in_img    = (const float*)d_in[1];
    const float* in_txt    = (const float*)d_in[2];
    const float* sa_w_in   = (const float*)d_in[3];
    const float* sa_b_in   = (const float*)d_in[4];
    const float* sa_w_out  = (const float*)d_in[5];
    const float* sa_b_out  = (const float*)d_in[6];
    const float* ca_w_in   = (const float*)d_in[7];
    const float* ca_b_in   = (const float*)d_in[8];
    const float* ca_w_out  = (const float*)d_in[9];
    const float* ca_b_out  = (const float*)d_in[10];
    const float* gate_img_w= (const float*)d_in[11];
    const float* gate_img_b= (const float*)d_in[12];
    const float* gate_txt_w= (const float*)d_in[13];
    const float* gate_txt_b= (const float*)d_in[14];
    const float* e_w1      = (const float*)d_in[15];
    const float* e_b1      = (const float*)d_in[16];
    const float* e_w2      = (const float*)d_in[17];
    const float* e_b2      = (const float*)d_in[18];
    const float* lnq_g     = (const float*)d_in[19];
    const float* lnq_b     = (const float*)d_in[20];
    const float* lnc_g     = (const float*)d_in[21];
    const float* lnc_b     = (const float*)d_in[22];
    const float* lnf_g     = (const float*)d_in[23];
    const float* lnf_b     = (const float*)d_in[24];
    float* out_q   = (float*)d_out;
    float* out_img = out_q + (size_t)BB * TT * HH;

    float *p_ln, *p_q, *p_cq, *p_qkv, *p_kv, *p_scores, *p_attn, *p_vt, *p_h, *p_acc;
    float *p_ctx_img, *p_ctx_txt, *p_gb_img, *p_gb_txt, *p_probs_t, *p_probs_i;
    int *p_sel_t, *p_sel_i, *p_cnt;
    cudaGetSymbolAddress((void**)&p_ln, g_ln);
    cudaGetSymbolAddress((void**)&p_q, g_q);
    cudaGetSymbolAddress((void**)&p_cq, g_cq);
    cudaGetSymbolAddress((void**)&p_qkv, g_qkv);
    cudaGetSymbolAddress((void**)&p_kv, g_kv);
    cudaGetSymbolAddress((void**)&p_scores, g_scores);
    cudaGetSymbolAddress((void**)&p_attn, g_attn);
    cudaGetSymbolAddress((void**)&p_vt, g_vt);
    cudaGetSymbolAddress((void**)&p_h, g_h);
    cudaGetSymbolAddress((void**)&p_acc, g_acc);
    cudaGetSymbolAddress((void**)&p_ctx_img, g_ctx_img);
    cudaGetSymbolAddress((void**)&p_ctx_txt, g_ctx_txt);
    cudaGetSymbolAddress((void**)&p_gb_img, g_gb_img);
    cudaGetSymbolAddress((void**)&p_gb_txt, g_gb_txt);
    cudaGetSymbolAddress((void**)&p_probs_t, g_probs_t);
    cudaGetSymbolAddress((void**)&p_probs_i, g_probs_i);
    cudaGetSymbolAddress((void**)&p_sel_t, g_sel_t);
    cudaGetSymbolAddress((void**)&p_sel_i, g_sel_i);
    cudaGetSymbolAddress((void**)&p_cnt, g_cnt);

    cudaFuncSetAttribute(k_gemm_r, cudaFuncAttributeMaxDynamicSharedMemorySize, SMEM128);
    cudaFuncSetAttribute(k_gemm_p, cudaFuncAttributeMaxDynamicSharedMemorySize, SMEM128);
    cudaFuncSetAttribute(k_scores, cudaFuncAttributeMaxDynamicSharedMemorySize, SMEM128);
    cudaFuncSetAttribute(k_av,     cudaFuncAttributeMaxDynamicSharedMemorySize, SMEM64);
    cudaFuncSetAttribute(k_moe1,   cudaFuncAttributeMaxDynamicSharedMemorySize, SMEM128);
    cudaFuncSetAttribute(k_moe2,   cudaFuncAttributeMaxDynamicSharedMemorySize, SMEM128);

    // ---- self attention ----
    k_ln<<<BB * TT, 256>>>(in_q, lnq_g, lnq_b, p_ln, BB * TT);
    k_gemm_r<<<dim3(3 * HH / 128, BB * TT / BM), 256, SMEM128>>>(
        p_ln, HH, sa_w_in, HH, sa_b_in, nullptr, p_qkv, 3 * HH,
        BB * TT, 3 * HH, HH);
    k_transp<<<dim3(TT / 32, 2, BB * NHH), dim3(32, 8)>>>(
        p_qkv + 2 * HH, 3 * HH, p_vt, TT);
    k_scores<<<dim3(TT / 128, TT / BM, BB * NHH), 256, SMEM128>>>(
        p_qkv, TT * 3 * HH, 3 * HH, p_qkv + HH, TT * 3 * HH, 3 * HH,
        p_scores, TT, TT);
    k_softmax_w<TT><<<BB * NHH * TT / 8, 256>>>(p_scores);
    k_av<<<dim3(1, TT / BM, BB * NHH), 256, SMEM64>>>(p_scores, p_vt, p_attn, TT, TT);
    k_gemm_p<<<dim3(HH / 128, BB * TT / BM), 256, SMEM128>>>(
        p_attn, HH, sa_w_out, HH, sa_b_out, in_q, p_q, HH, BB * TT, HH, HH);

    // ---- cross attention ----
    k_ln<<<BB * TT, 256>>>(p_q, lnc_g, lnc_b, p_ln, BB * TT);
    k_gemm_r<<<dim3(HH / 128, BB * TT / BM), 256, SMEM128>>>(
        p_ln, HH, ca_w_in, HH, ca_b_in, nullptr, p_cq, HH, BB * TT, HH, HH);
    k_gemm_r<<<dim3(2 * HH / 128, BB * VV / BM), 256, SMEM128>>>(
        in_img, HH, ca_w_in + (size_t)HH * HH, HH, ca_b_in + HH, nullptr,
        p_kv, 2 * HH, BB * VV, 2 * HH, HH);
    k_transp<<<dim3(VV / 32, 2, BB * NHH), dim3(32, 8)>>>(
        p_kv + HH, 2 * HH, p_vt, VV);
    k_scores<<<dim3((VV + 127) / 128, TT / BM, BB * NHH), 256, SMEM128>>>(
        p_cq, TT * HH, HH, p_kv, VV * 2 * HH, 2 * HH, p_scores, TT, VV);
    k_softmax_w<VV><<<BB * NHH * TT / 8, 256>>>(p_scores);
    k_av<<<dim3(1, TT / BM, BB * NHH), 256, SMEM64>>>(p_scores, p_vt, p_attn, TT, VV);
    k_gemm_p<<<dim3(HH / 128, BB * TT / BM), 256, SMEM128>>>(
        p_attn, HH, ca_w_out, HH, ca_b_out, p_q, p_q, HH, BB * TT, HH, HH);

    // ---- gating ----
    k_mean<<<dim3(HH / 256, BB), 256>>>(in_img, p_ctx_img, VV);
    k_mean<<<dim3(HH / 256, BB), 256>>>(in_txt, p_ctx_txt, LL);
    k_ctxbias<<<BB * EE, 256>>>(p_ctx_txt, gate_img_w, gate_img_b, p_gb_img);
    k_ctxbias<<<BB * EE, 256>>>(p_ctx_img, gate_txt_w, gate_txt_b, p_gb_txt);
    k_gate<<<BB * VV, 256>>>(in_img, gate_img_w, p_gb_img, p_probs_i, VV);
    k_gate<<<BB * TT, 256>>>(p_q, gate_txt_w, p_gb_txt, p_probs_t, TT);
    k_topk<<<BB * EE, 256>>>(p_probs_t, TT, KSEL_T, p_sel_t);
    k_topk<<<BB * EE, 256>>>(p_probs_i, VV, KSEL_V, p_sel_i);

    // ---- text-stream MoE ----
    k_ln<<<BB * TT, 256>>>(p_q, lnf_g, lnf_b, p_ln, BB * TT);
    k_fillf<<<(BB * TT * HH + 255) / 256, 256>>>(p_acc, BB * TT * HH);
    k_zeroi<<<(BB * VV + 255) / 256, 256>>>(p_cnt, BB * VV);
    k_count<<<BB * EE, 128>>>(p_sel_t, p_cnt, TT, KSEL_T);
    k_moe1<<<dim3(II / 128, 1, BB * EE), 256, SMEM128>>>(
        p_ln, e_w1, e_b1, p_sel_t, p_h, TT, KSEL_T);
    k_moe2<<<dim3(HH / 128, 1, BB * EE), 256, SMEM128>>>(
        p_h, e_w2, e_b2, p_sel_t, p_acc, TT, KSEL_T);
    k_combine<<<(BB * TT * HH + 255) / 256, 256>>>(
        p_q, p_acc, p_cnt, out_q, BB * TT * HH);

    // ---- image-stream MoE ----
    k_fillf<<<(BB * VV * HH + 255) / 256, 256>>>(p_acc, BB * VV * HH);
    k_zeroi<<<(BB * VV + 255) / 256, 256>>>(p_cnt, BB * VV);
    k_count<<<BB * EE, 128>>>(p_sel_i, p_cnt, VV, KSEL_V);
    k_moe1<<<dim3(II / 128, 1, BB * EE), 256, SMEM128>>>(
        in_img, e_w1, e_b1, p_sel_i, p_h, VV, KSEL_V);
    k_moe2<<<dim3(HH / 128, 1, BB * EE), 256, SMEM128>>>(
        p_h, e_w2, e_b2, p_sel_i, p_acc, VV, KSEL_V);
    k_combine<<<(BB * VV * HH + 255) / 256, 256>>>(
        in_img, p_acc, p_cnt, out_img, BB * VV * HH);
}